// round 1
// baseline (speedup 1.0000x reference)
#include <cuda_runtime.h>
#include <math.h>

#define BB 4
#define TT 2048
#define CC 1024
#define HH 16
#define DD 64

// Scratch (static device globals — allocation-guard safe)
__device__ float g_q[BB * HH * TT * DD];   // [B,H,T,D]
__device__ float g_k[BB * HH * TT * DD];
__device__ float g_v[BB * HH * TT * DD];
__device__ float g_ao[BB * TT * CC];       // attention output, [B,T,C]

// ---------------------------------------------------------------------------
// Tiled fp32 GEMM: C = A[M,K] @ B[K,N] + bias[N]
// MODE 0: scatter into g_q/g_k/g_v ([B,H,T,D])   MODE 1: write Cout row-major
// BM=BN=128, BK=8, 256 threads, 8x8 per thread.
// ---------------------------------------------------------------------------
template <int MODE>
__global__ __launch_bounds__(256) void gemm_k(
    const float* __restrict__ A, const float* __restrict__ Bw,
    const float* __restrict__ bias, float* __restrict__ Cout,
    int M, int N, int K)
{
    __shared__ float As[8][128];   // transposed A tile
    __shared__ float Bs[8][128];

    const int bm  = blockIdx.y * 128;
    const int bn  = blockIdx.x * 128;
    const int tid = threadIdx.x;
    const int tx  = tid & 15;      // 0..15  (N dir)
    const int ty  = tid >> 4;      // 0..15  (M dir)

    // global->smem load indices
    const int arow = tid >> 1;           // 0..127
    const int acol = (tid & 1) * 4;      // 0 or 4
    const int brow = tid >> 5;           // 0..7
    const int bcol = (tid & 31) * 4;     // 0..124

    float acc[8][8];
#pragma unroll
    for (int i = 0; i < 8; i++)
#pragma unroll
        for (int j = 0; j < 8; j++) acc[i][j] = 0.f;

    const float* Aptr = A + (size_t)(bm + arow) * K + acol;
    const float* Bptr = Bw + (size_t)brow * N + bn + bcol;

    for (int k0 = 0; k0 < K; k0 += 8) {
        float4 a4 = *(const float4*)(Aptr + k0);
        float4 b4 = *(const float4*)(Bptr + (size_t)k0 * N);
        As[acol + 0][arow] = a4.x;
        As[acol + 1][arow] = a4.y;
        As[acol + 2][arow] = a4.z;
        As[acol + 3][arow] = a4.w;
        *(float4*)&Bs[brow][bcol] = b4;
        __syncthreads();

#pragma unroll
        for (int kk = 0; kk < 8; kk++) {
            float af[8], bf[8];
            *(float4*)(af)     = *(const float4*)&As[kk][ty * 8];
            *(float4*)(af + 4) = *(const float4*)&As[kk][ty * 8 + 4];
            *(float4*)(bf)     = *(const float4*)&Bs[kk][tx * 8];
            *(float4*)(bf + 4) = *(const float4*)&Bs[kk][tx * 8 + 4];
#pragma unroll
            for (int i = 0; i < 8; i++)
#pragma unroll
                for (int j = 0; j < 8; j++)
                    acc[i][j] = fmaf(af[i], bf[j], acc[i][j]);
        }
        __syncthreads();
    }

#pragma unroll
    for (int i = 0; i < 8; i++) {
        const int m = bm + ty * 8 + i;
#pragma unroll
        for (int j = 0; j < 8; j++) {
            const int n = bn + tx * 8 + j;
            const float vv = acc[i][j] + bias[n];
            if (MODE == 0) {
                // n in [0,3C): which third, head, dim; m = b*T + t
                const int which = n >> 10;
                const int c1 = n & 1023;
                const int h = c1 >> 6, d = c1 & 63;
                const int b = m >> 11, t = m & 2047;
                float* dst = (which == 0) ? g_q : (which == 1) ? g_k : g_v;
                dst[(((size_t)(b * HH + h)) * TT + t) * DD + d] = vv;
            } else {
                Cout[(size_t)m * N + n] = vv;
            }
        }
    }
}

// ---------------------------------------------------------------------------
// Causal flash attention, fp32. One block = one (b,h) x 64-query tile.
// 64 threads, 8x8 register fragments for S and O. Online softmax; stats
// stay in registers (replicated across the tc shuffle group).
// Dynamic smem: Qs/Ks/Vs/Ps, each 64x65 floats (pad kills 8-way conflicts).
// ---------------------------------------------------------------------------
__global__ __launch_bounds__(64) void flash_k()
{
    extern __shared__ float sm[];
    float* Qs = sm;                 // [64][65]
    float* Ks = Qs + 64 * 65;
    float* Vs = Ks + 64 * 65;
    float* Ps = Vs + 64 * 65;

    const int qt  = blockIdx.x;     // query tile (0..31)
    const int bh  = blockIdx.y;     // b*H + h   (0..63)
    const int tid = threadIdx.x;    // 0..63
    const int tr  = tid >> 3;       // 0..7 (row group)
    const int tc  = tid & 7;        // 0..7 (col group)

    // load Q tile (coalesced)
    const float* qb = g_q + ((size_t)bh * TT + qt * 64) * DD;
    for (int idx = tid; idx < 64 * 64; idx += 64)
        Qs[(idx >> 6) * 65 + (idx & 63)] = qb[idx];

    float accO[8][8];
    float m_[8], l_[8];
#pragma unroll
    for (int i = 0; i < 8; i++) {
        m_[i] = -INFINITY;
        l_[i] = 0.f;
#pragma unroll
        for (int j = 0; j < 8; j++) accO[i][j] = 0.f;
    }
    __syncthreads();

    const float scale = 0.125f;     // 1/sqrt(64)

    for (int kt = 0; kt <= qt; kt++) {
        const float* kb = g_k + ((size_t)bh * TT + kt * 64) * DD;
        const float* vb = g_v + ((size_t)bh * TT + kt * 64) * DD;
        for (int idx = tid; idx < 64 * 64; idx += 64) {
            const int r = idx >> 6, c = idx & 63;
            Ks[r * 65 + c] = kb[idx];
            Vs[r * 65 + c] = vb[idx];
        }
        __syncthreads();

        // S = Q @ K^T  (8x8 fragment per thread)
        float accS[8][8];
#pragma unroll
        for (int i = 0; i < 8; i++)
#pragma unroll
            for (int j = 0; j < 8; j++) accS[i][j] = 0.f;

        for (int d = 0; d < 64; d++) {
            float qf[8], kf[8];
#pragma unroll
            for (int i = 0; i < 8; i++) qf[i] = Qs[(tr * 8 + i) * 65 + d];
#pragma unroll
            for (int j = 0; j < 8; j++) kf[j] = Ks[(tc * 8 + j) * 65 + d];
#pragma unroll
            for (int i = 0; i < 8; i++)
#pragma unroll
                for (int j = 0; j < 8; j++)
                    accS[i][j] = fmaf(qf[i], kf[j], accS[i][j]);
        }

        // scale + causal mask (only the diagonal tile has masked entries)
        if (kt == qt) {
#pragma unroll
            for (int i = 0; i < 8; i++)
#pragma unroll
                for (int j = 0; j < 8; j++)
                    accS[i][j] = (tc * 8 + j > tr * 8 + i) ? -1e30f
                                                           : accS[i][j] * scale;
        } else {
#pragma unroll
            for (int i = 0; i < 8; i++)
#pragma unroll
                for (int j = 0; j < 8; j++) accS[i][j] *= scale;
        }

        // online softmax update (stats replicated across tc group)
#pragma unroll
        for (int i = 0; i < 8; i++) {
            float mx = accS[i][0];
#pragma unroll
            for (int j = 1; j < 8; j++) mx = fmaxf(mx, accS[i][j]);
            mx = fmaxf(mx, __shfl_xor_sync(0xffffffffu, mx, 1));
            mx = fmaxf(mx, __shfl_xor_sync(0xffffffffu, mx, 2));
            mx = fmaxf(mx, __shfl_xor_sync(0xffffffffu, mx, 4));

            const float mnew  = fmaxf(m_[i], mx);
            const float alpha = __expf(m_[i] - mnew);
            float ls = 0.f;
#pragma unroll
            for (int j = 0; j < 8; j++) {
                const float p = __expf(accS[i][j] - mnew);
                accS[i][j] = p;
                ls += p;
            }
            ls += __shfl_xor_sync(0xffffffffu, ls, 1);
            ls += __shfl_xor_sync(0xffffffffu, ls, 2);
            ls += __shfl_xor_sync(0xffffffffu, ls, 4);

            l_[i] = l_[i] * alpha + ls;
            m_[i] = mnew;
#pragma unroll
            for (int j = 0; j < 8; j++) accO[i][j] *= alpha;
        }

        // P -> smem, then O += P @ V
#pragma unroll
        for (int i = 0; i < 8; i++)
#pragma unroll
            for (int j = 0; j < 8; j++)
                Ps[(tr * 8 + i) * 65 + tc * 8 + j] = accS[i][j];
        __syncthreads();

        for (int j = 0; j < 64; j++) {
            float pf[8], vf[8];
#pragma unroll
            for (int i = 0; i < 8; i++) pf[i] = Ps[(tr * 8 + i) * 65 + j];
#pragma unroll
            for (int jj = 0; jj < 8; jj++) vf[jj] = Vs[j * 65 + tc * 8 + jj];
#pragma unroll
            for (int i = 0; i < 8; i++)
#pragma unroll
                for (int jj = 0; jj < 8; jj++)
                    accO[i][jj] = fmaf(pf[i], vf[jj], accO[i][jj]);
        }
        __syncthreads();   // protect Ks/Vs/Ps before next iteration rewrites
    }

    // write O / l  into [B,T,C] for the projection GEMM
    const int b = bh >> 4, h = bh & 15;
#pragma unroll
    for (int i = 0; i < 8; i++) {
        const float inv = 1.f / l_[i];
        const int t = qt * 64 + tr * 8 + i;
        float* op = g_ao + ((size_t)(b * TT + t)) * CC + h * 64 + tc * 8;
#pragma unroll
        for (int jj = 0; jj < 8; jj++) op[jj] = accO[i][jj] * inv;
    }
}

// ---------------------------------------------------------------------------
extern "C" void kernel_launch(void* const* d_in, const int* in_sizes, int n_in,
                              void* d_out, int out_size)
{
    const float* x  = (const float*)d_in[0];   // [4,2048,1024]
    const float* Wa = (const float*)d_in[1];   // [1024,3072]
    const float* ba = (const float*)d_in[2];   // [3072]
    const float* Wp = (const float*)d_in[3];   // [1024,1024]
    const float* bp = (const float*)d_in[4];   // [1024]
    float* out = (float*)d_out;                // [4,2048,1024]

    void* p_ao = nullptr;
    cudaGetSymbolAddress(&p_ao, g_ao);

    // 1) QKV GEMM + bias, scatter to [B,H,T,D]
    gemm_k<0><<<dim3(3072 / 128, 8192 / 128), 256>>>(
        x, Wa, ba, nullptr, 8192, 3072, 1024);

    // 2) causal flash attention
    const int FLASH_SMEM = 4 * 64 * 65 * (int)sizeof(float);  // 66560 B
    cudaFuncSetAttribute(flash_k, cudaFuncAttributeMaxDynamicSharedMemorySize,
                         FLASH_SMEM);
    flash_k<<<dim3(TT / 64, BB * HH), 64, FLASH_SMEM>>>();

    // 3) output projection + bias
    gemm_k<1><<<dim3(1024 / 128, 8192 / 128), 256>>>(
        (const float*)p_ao, Wp, bp, out, 8192, 1024, 1024);
}

// round 3
// speedup vs baseline: 2.9899x; 2.9899x over previous
#include <cuda_runtime.h>
#include <math.h>
#include <cstdint>

#define BB 4
#define TT 2048
#define CC 1024
#define HH 16
#define DD 64

// Scratch (static device globals — allocation-guard safe)
__device__ float g_q[BB * HH * TT * DD];   // [B,H,T,D]
__device__ float g_k[BB * HH * TT * DD];
__device__ float g_v[BB * HH * TT * DD];
__device__ float g_ao[BB * TT * CC];       // attention output, [B,T,C]

// ---------------------------------------------------------------------------
__device__ __forceinline__ uint32_t f2tf32(float x) {
    uint32_t u;
    asm("cvt.rna.tf32.f32 %0, %1;" : "=r"(u) : "f"(x));
    return u;
}

// m16n8k8 tf32 MMA, D += A*B (fp32 accumulate, in-place)
__device__ __forceinline__ void mma8(float* d, const uint32_t* a,
                                     uint32_t b0, uint32_t b1) {
    asm volatile(
        "mma.sync.aligned.m16n8k8.row.col.f32.tf32.tf32.f32 "
        "{%0,%1,%2,%3}, {%4,%5,%6,%7}, {%8,%9}, {%0,%1,%2,%3};"
        : "+f"(d[0]), "+f"(d[1]), "+f"(d[2]), "+f"(d[3])
        : "r"(a[0]), "r"(a[1]), "r"(a[2]), "r"(a[3]), "r"(b0), "r"(b1));
}

// ---------------------------------------------------------------------------
// tf32 mma.sync GEMM: C[M,N] = A[M,K] @ B[K,N] + bias.
// 128x128 tile, BK=32, 256 threads (8 warps, 4x2). Warp tile 32x64.
// MODE 0: scatter into g_q/g_k/g_v ([B,H,T,D]).  MODE 1: Cout row-major.
// ---------------------------------------------------------------------------
template <int MODE>
__global__ __launch_bounds__(256) void gemm_mma(
    const float* __restrict__ A, const float* __restrict__ Bw,
    const float* __restrict__ bias, float* __restrict__ Cout,
    int M, int N, int K)
{
    __shared__ uint32_t As[128 * 36];   // stride 36 (=4 mod 32): A-frag conflict-free
    __shared__ uint32_t Bs[32 * 136];   // stride 136 (=8 mod 32): B-frag conflict-free

    const int tid  = threadIdx.x;
    const int lane = tid & 31, warp = tid >> 5;
    const int wm = warp >> 1, wn = warp & 1;
    const int g = lane >> 2, t = lane & 3;
    const int bm = blockIdx.y * 128, bn = blockIdx.x * 128;

    float acc[2][8][4];
#pragma unroll
    for (int i = 0; i < 2; i++)
#pragma unroll
        for (int j = 0; j < 8; j++)
#pragma unroll
            for (int c = 0; c < 4; c++) acc[i][j][c] = 0.f;

    for (int k0 = 0; k0 < K; k0 += 32) {
        // A tile: 128 x 32
#pragma unroll
        for (int p = 0; p < 4; p++) {
            const int idx = tid + (p << 8);
            const int row = idx >> 3, cq = (idx & 7) << 2;
            float4 a = *(const float4*)(A + (size_t)(bm + row) * K + k0 + cq);
            uint4 u;
            u.x = f2tf32(a.x); u.y = f2tf32(a.y);
            u.z = f2tf32(a.z); u.w = f2tf32(a.w);
            *(uint4*)&As[row * 36 + cq] = u;
        }
        // B tile: 32 x 128
#pragma unroll
        for (int p = 0; p < 4; p++) {
            const int idx = tid + (p << 8);
            const int kr = idx >> 5, nq = (idx & 31) << 2;
            float4 b = *(const float4*)(Bw + (size_t)(k0 + kr) * N + bn + nq);
            uint4 u;
            u.x = f2tf32(b.x); u.y = f2tf32(b.y);
            u.z = f2tf32(b.z); u.w = f2tf32(b.w);
            *(uint4*)&Bs[kr * 136 + nq] = u;
        }
        __syncthreads();

#pragma unroll
        for (int ks = 0; ks < 4; ks++) {
            const int kk = ks << 3;
            uint32_t aF[2][4];
#pragma unroll
            for (int i = 0; i < 2; i++) {
                const int mr = wm * 32 + i * 16;
                aF[i][0] = As[(mr + g) * 36 + kk + t];
                aF[i][1] = As[(mr + 8 + g) * 36 + kk + t];
                aF[i][2] = As[(mr + g) * 36 + kk + t + 4];
                aF[i][3] = As[(mr + 8 + g) * 36 + kk + t + 4];
            }
#pragma unroll
            for (int j = 0; j < 8; j++) {
                const int nb = wn * 64 + j * 8;
                const uint32_t b0 = Bs[(kk + t) * 136 + nb + g];
                const uint32_t b1 = Bs[(kk + t + 4) * 136 + nb + g];
                mma8(acc[0][j], aF[0], b0, b1);
                mma8(acc[1][j], aF[1], b0, b1);
            }
        }
        __syncthreads();
    }

    // epilogue: C-frag (rows g,g+8; cols 2t,2t+1) -> global with bias
#pragma unroll
    for (int i = 0; i < 2; i++) {
        const int mrow = bm + wm * 32 + i * 16;
#pragma unroll
        for (int j = 0; j < 8; j++) {
            const int nb = bn + wn * 64 + j * 8 + t * 2;
            const float bx = bias[nb], by = bias[nb + 1];
#pragma unroll
            for (int h = 0; h < 2; h++) {
                const int row = mrow + g + h * 8;
                float2 v;
                v.x = acc[i][j][h * 2 + 0] + bx;
                v.y = acc[i][j][h * 2 + 1] + by;
                if (MODE == 0) {
                    const int which = nb >> 10;
                    const int c1 = nb & 1023;
                    const int hh = c1 >> 6, d = c1 & 63;
                    const int b = row >> 11, tt = row & 2047;
                    float* dst = (which == 0) ? g_q : (which == 1) ? g_k : g_v;
                    *(float2*)&dst[(((size_t)(b * HH + hh)) * TT + tt) * DD + d] = v;
                } else {
                    *(float2*)&Cout[(size_t)row * N + nb] = v;
                }
            }
        }
    }
}

// ---------------------------------------------------------------------------
// Causal flash attention with tf32 mma.sync. One block = (b,h) x 64-query tile.
// 128 threads (4 warps); warp w owns query rows [w*16, w*16+16).
// Smem strides: 68 for A/K-style frag access (4g+t distinct banks),
//               72 for V B-style frag access (8t+g distinct banks).
// ---------------------------------------------------------------------------
__global__ __launch_bounds__(128) void flash_mma()
{
    extern __shared__ uint32_t sm[];
    uint32_t* Qs = sm;               // [64][68]
    uint32_t* Ks = Qs + 64 * 68;     // [64][68]
    uint32_t* Vs = Ks + 64 * 68;     // [64][72]
    uint32_t* Ps = Vs + 64 * 72;     // [64][68]

    const int qt = blockIdx.x, bh = blockIdx.y;
    const int tid = threadIdx.x, lane = tid & 31, w = tid >> 5;
    const int g = lane >> 2, t = lane & 3;
    const int mr = w * 16;

    // load Q tile (tf32-converted)
    const float* qb = g_q + ((size_t)bh * TT + qt * 64) * DD;
#pragma unroll
    for (int p = 0; p < 8; p++) {
        const int idx = tid + (p << 7);
        const int row = idx >> 4, c4 = (idx & 15) << 2;
        float4 a = *(const float4*)(qb + row * 64 + c4);
        uint4 u;
        u.x = f2tf32(a.x); u.y = f2tf32(a.y);
        u.z = f2tf32(a.z); u.w = f2tf32(a.w);
        *(uint4*)&Qs[row * 68 + c4] = u;
    }

    float accO[8][4];
#pragma unroll
    for (int j = 0; j < 8; j++)
#pragma unroll
        for (int c = 0; c < 4; c++) accO[j][c] = 0.f;
    float m0 = -INFINITY, m1 = -INFINITY, l0 = 0.f, l1 = 0.f;

    const float scale = 0.125f;

    for (int kt = 0; kt <= qt; kt++) {
        const float* kb = g_k + ((size_t)bh * TT + kt * 64) * DD;
        const float* vb = g_v + ((size_t)bh * TT + kt * 64) * DD;
#pragma unroll
        for (int p = 0; p < 8; p++) {
            const int idx = tid + (p << 7);
            const int row = idx >> 4, c4 = (idx & 15) << 2;
            float4 a = *(const float4*)(kb + row * 64 + c4);
            uint4 u;
            u.x = f2tf32(a.x); u.y = f2tf32(a.y);
            u.z = f2tf32(a.z); u.w = f2tf32(a.w);
            *(uint4*)&Ks[row * 68 + c4] = u;
            float4 b = *(const float4*)(vb + row * 64 + c4);
            uint4 v;
            v.x = f2tf32(b.x); v.y = f2tf32(b.y);
            v.z = f2tf32(b.z); v.w = f2tf32(b.w);
            *(uint4*)&Vs[row * 72 + c4] = v;
        }
        __syncthreads();

        // S = Q @ K^T : warp computes 16x64
        float accS[8][4];
#pragma unroll
        for (int j = 0; j < 8; j++)
#pragma unroll
            for (int c = 0; c < 4; c++) accS[j][c] = 0.f;

#pragma unroll
        for (int ks = 0; ks < 8; ks++) {
            const int kk = ks << 3;
            uint32_t aF[4];
            aF[0] = Qs[(mr + g) * 68 + kk + t];
            aF[1] = Qs[(mr + 8 + g) * 68 + kk + t];
            aF[2] = Qs[(mr + g) * 68 + kk + t + 4];
            aF[3] = Qs[(mr + 8 + g) * 68 + kk + t + 4];
#pragma unroll
            for (int j = 0; j < 8; j++) {
                const uint32_t b0 = Ks[(j * 8 + g) * 68 + kk + t];
                const uint32_t b1 = Ks[(j * 8 + g) * 68 + kk + t + 4];
                mma8(accS[j], aF, b0, b1);
            }
        }

        // scale + causal mask (diagonal tile only)
        const int r0l = mr + g, r1l = mr + 8 + g;
        if (kt == qt) {
#pragma unroll
            for (int j = 0; j < 8; j++) {
                const int cb = j * 8 + 2 * t;
                accS[j][0] = (cb     <= r0l) ? accS[j][0] * scale : -1e30f;
                accS[j][1] = (cb + 1 <= r0l) ? accS[j][1] * scale : -1e30f;
                accS[j][2] = (cb     <= r1l) ? accS[j][2] * scale : -1e30f;
                accS[j][3] = (cb + 1 <= r1l) ? accS[j][3] * scale : -1e30f;
            }
        } else {
#pragma unroll
            for (int j = 0; j < 8; j++)
#pragma unroll
                for (int c = 0; c < 4; c++) accS[j][c] *= scale;
        }

        // online softmax (rows r0 = mr+g, r1 = mr+8+g; 4-lane t-group reduce)
        float mx0 = -1e30f, mx1 = -1e30f;
#pragma unroll
        for (int j = 0; j < 8; j++) {
            mx0 = fmaxf(mx0, fmaxf(accS[j][0], accS[j][1]));
            mx1 = fmaxf(mx1, fmaxf(accS[j][2], accS[j][3]));
        }
        mx0 = fmaxf(mx0, __shfl_xor_sync(0xffffffffu, mx0, 1));
        mx0 = fmaxf(mx0, __shfl_xor_sync(0xffffffffu, mx0, 2));
        mx1 = fmaxf(mx1, __shfl_xor_sync(0xffffffffu, mx1, 1));
        mx1 = fmaxf(mx1, __shfl_xor_sync(0xffffffffu, mx1, 2));

        const float mn0 = fmaxf(m0, mx0), mn1 = fmaxf(m1, mx1);
        const float al0 = __expf(m0 - mn0), al1 = __expf(m1 - mn1);
        float s0 = 0.f, s1 = 0.f;
#pragma unroll
        for (int j = 0; j < 8; j++) {
            accS[j][0] = __expf(accS[j][0] - mn0); s0 += accS[j][0];
            accS[j][1] = __expf(accS[j][1] - mn0); s0 += accS[j][1];
            accS[j][2] = __expf(accS[j][2] - mn1); s1 += accS[j][2];
            accS[j][3] = __expf(accS[j][3] - mn1); s1 += accS[j][3];
        }
        s0 += __shfl_xor_sync(0xffffffffu, s0, 1);
        s0 += __shfl_xor_sync(0xffffffffu, s0, 2);
        s1 += __shfl_xor_sync(0xffffffffu, s1, 1);
        s1 += __shfl_xor_sync(0xffffffffu, s1, 2);

        l0 = l0 * al0 + s0;  m0 = mn0;
        l1 = l1 * al1 + s1;  m1 = mn1;
#pragma unroll
        for (int j = 0; j < 8; j++) {
            accO[j][0] *= al0; accO[j][1] *= al0;
            accO[j][2] *= al1; accO[j][3] *= al1;
        }

        // P -> smem (tf32), per-warp private rows
        uint32_t* Pw0 = Ps + (mr + g) * 68;
        uint32_t* Pw1 = Ps + (mr + 8 + g) * 68;
#pragma unroll
        for (int j = 0; j < 8; j++) {
            const int cb = j * 8 + 2 * t;
            Pw0[cb]     = f2tf32(accS[j][0]);
            Pw0[cb + 1] = f2tf32(accS[j][1]);
            Pw1[cb]     = f2tf32(accS[j][2]);
            Pw1[cb + 1] = f2tf32(accS[j][3]);
        }
        __syncwarp();

        // O += P @ V
#pragma unroll
        for (int ks = 0; ks < 8; ks++) {
            const int kk = ks << 3;
            uint32_t aF[4];
            aF[0] = Ps[(mr + g) * 68 + kk + t];
            aF[1] = Ps[(mr + 8 + g) * 68 + kk + t];
            aF[2] = Ps[(mr + g) * 68 + kk + t + 4];
            aF[3] = Ps[(mr + 8 + g) * 68 + kk + t + 4];
#pragma unroll
            for (int j = 0; j < 8; j++) {
                const uint32_t b0 = Vs[(kk + t) * 72 + j * 8 + g];
                const uint32_t b1 = Vs[(kk + t + 4) * 72 + j * 8 + g];
                mma8(accO[j], aF, b0, b1);
            }
        }
        __syncthreads();   // protect Ks/Vs before next tile load
    }

    // normalize + write to g_ao [B,T,C]
    const float inv0 = 1.f / l0, inv1 = 1.f / l1;
    const int b = bh >> 4, h = bh & 15;
    const int r0 = qt * 64 + mr + g, r1 = r0 + 8;
#pragma unroll
    for (int j = 0; j < 8; j++) {
        const int col = h * 64 + j * 8 + 2 * t;
        float2 v0, v1;
        v0.x = accO[j][0] * inv0; v0.y = accO[j][1] * inv0;
        v1.x = accO[j][2] * inv1; v1.y = accO[j][3] * inv1;
        *(float2*)&g_ao[((size_t)(b * TT + r0)) * CC + col] = v0;
        *(float2*)&g_ao[((size_t)(b * TT + r1)) * CC + col] = v1;
    }
}

// ---------------------------------------------------------------------------
extern "C" void kernel_launch(void* const* d_in, const int* in_sizes, int n_in,
                              void* d_out, int out_size)
{
    const float* x  = (const float*)d_in[0];   // [4,2048,1024]
    const float* Wa = (const float*)d_in[1];   // [1024,3072]
    const float* ba = (const float*)d_in[2];   // [3072]
    const float* Wp = (const float*)d_in[3];   // [1024,1024]
    const float* bp = (const float*)d_in[4];   // [1024]
    float* out = (float*)d_out;                // [4,2048,1024]

    void* p_ao = nullptr;
    cudaGetSymbolAddress(&p_ao, g_ao);

    // 1) QKV GEMM + bias, scatter to [B,H,T,D]  (tf32 mma.sync)
    gemm_mma<0><<<dim3(3072 / 128, 8192 / 128), 256>>>(
        x, Wa, ba, nullptr, 8192, 3072, 1024);

    // 2) causal flash attention (tf32 mma.sync)
    const int FLASH_SMEM = (64 * 68 * 3 + 64 * 72) * (int)sizeof(uint32_t); // 70656
    cudaFuncSetAttribute(flash_mma, cudaFuncAttributeMaxDynamicSharedMemorySize,
                         FLASH_SMEM);
    flash_mma<<<dim3(TT / 64, BB * HH), 128, FLASH_SMEM>>>();

    // 3) output projection + bias  (tf32 mma.sync)
    gemm_mma<1><<<dim3(1024 / 128, 8192 / 128), 256>>>(
        (const float*)p_ao, Wp, bp, out, 8192, 1024, 1024);
}

// round 4
// speedup vs baseline: 4.1104x; 1.3748x over previous
#include <cuda_runtime.h>
#include <math.h>
#include <cstdint>

#define BB 4
#define TT 2048
#define CC 1024
#define HH 16
#define DD 64

// Scratch (static device globals — allocation-guard safe)
__device__ float g_q[BB * HH * TT * DD];   // [B,H,T,D]
__device__ float g_k[BB * HH * TT * DD];
__device__ float g_v[BB * HH * TT * DD];
__device__ float g_ao[BB * TT * CC];       // attention output, [B,T,C]

// ---------------------------------------------------------------------------
__device__ __forceinline__ uint32_t f2tf32(float x) {
    uint32_t u;
    asm("cvt.rna.tf32.f32 %0, %1;" : "=r"(u) : "f"(x));
    return u;
}

// m16n8k8 tf32 MMA, D += A*B (fp32 accumulate, in-place)
__device__ __forceinline__ void mma8(float* d, const uint32_t* a,
                                     uint32_t b0, uint32_t b1) {
    asm volatile(
        "mma.sync.aligned.m16n8k8.row.col.f32.tf32.tf32.f32 "
        "{%0,%1,%2,%3}, {%4,%5,%6,%7}, {%8,%9}, {%0,%1,%2,%3};"
        : "+f"(d[0]), "+f"(d[1]), "+f"(d[2]), "+f"(d[3])
        : "r"(a[0]), "r"(a[1]), "r"(a[2]), "r"(a[3]), "r"(b0), "r"(b1));
}

// ---------------------------------------------------------------------------
// tf32 mma.sync GEMM, software-pipelined double buffer.
// C[M,N] = A[M,K] @ B[K,N] + bias. 128x128 tile, BK=32, 256 thr (8 warps 4x2).
// Per iter: LDG next -> mma current -> cvt+STS next -> 1 sync.
// Smem (dynamic, u32): As[2][128*36], Bs[2][32*136] = 71680 B.
// MODE 0: scatter into g_q/g_k/g_v.  MODE 1: Cout row-major.
// ---------------------------------------------------------------------------
template <int MODE>
__global__ __launch_bounds__(256) void gemm_mma(
    const float* __restrict__ A, const float* __restrict__ Bw,
    const float* __restrict__ bias, float* __restrict__ Cout,
    int M, int N, int K)
{
    extern __shared__ uint32_t sm[];
    const int tid  = threadIdx.x;
    const int lane = tid & 31, warp = tid >> 5;
    const int wm = warp >> 1, wn = warp & 1;
    const int g = lane >> 2, t = lane & 3;
    const int bm = blockIdx.y * 128, bn = blockIdx.x * 128;

    // per-thread load coords
    const int arow = tid >> 3, acq = (tid & 7) << 2;   // A: rows arow+32p
    const int bkr  = tid >> 5, bnq = (tid & 31) << 2;  // B: rows bkr+8p

    float4 ra[4], rb[4];
    float acc[2][8][4];
#pragma unroll
    for (int i = 0; i < 2; i++)
#pragma unroll
        for (int j = 0; j < 8; j++)
#pragma unroll
            for (int c = 0; c < 4; c++) acc[i][j][c] = 0.f;

    auto ldg_tile = [&](int k0) {
#pragma unroll
        for (int p = 0; p < 4; p++) {
            ra[p] = *(const float4*)(A + (size_t)(bm + arow + 32 * p) * K + k0 + acq);
            rb[p] = *(const float4*)(Bw + (size_t)(k0 + bkr + 8 * p) * N + bn + bnq);
        }
    };
    auto sts_tile = [&](int s) {
        uint32_t* As = sm + s * 4608;
        uint32_t* Bs = sm + 9216 + s * 4352;
#pragma unroll
        for (int p = 0; p < 4; p++) {
            uint4 u;
            u.x = f2tf32(ra[p].x); u.y = f2tf32(ra[p].y);
            u.z = f2tf32(ra[p].z); u.w = f2tf32(ra[p].w);
            *(uint4*)&As[(arow + 32 * p) * 36 + acq] = u;
            uint4 v;
            v.x = f2tf32(rb[p].x); v.y = f2tf32(rb[p].y);
            v.z = f2tf32(rb[p].z); v.w = f2tf32(rb[p].w);
            *(uint4*)&Bs[(bkr + 8 * p) * 136 + bnq] = v;
        }
    };
    auto compute = [&](int s) {
        const uint32_t* As = sm + s * 4608;
        const uint32_t* Bs = sm + 9216 + s * 4352;
#pragma unroll
        for (int ks = 0; ks < 4; ks++) {
            const int kk = ks << 3;
            uint32_t aF[2][4];
#pragma unroll
            for (int i = 0; i < 2; i++) {
                const int mr = wm * 32 + i * 16;
                aF[i][0] = As[(mr + g) * 36 + kk + t];
                aF[i][1] = As[(mr + 8 + g) * 36 + kk + t];
                aF[i][2] = As[(mr + g) * 36 + kk + t + 4];
                aF[i][3] = As[(mr + 8 + g) * 36 + kk + t + 4];
            }
#pragma unroll
            for (int j = 0; j < 8; j++) {
                const int nb = wn * 64 + j * 8;
                const uint32_t b0 = Bs[(kk + t) * 136 + nb + g];
                const uint32_t b1 = Bs[(kk + t + 4) * 136 + nb + g];
                mma8(acc[0][j], aF[0], b0, b1);
                mma8(acc[1][j], aF[1], b0, b1);
            }
        }
    };

    const int niter = K >> 5;
    ldg_tile(0);
    sts_tile(0);
    __syncthreads();
    for (int i = 0; i < niter; i++) {
        if (i + 1 < niter) ldg_tile((i + 1) << 5);
        compute(i & 1);
        if (i + 1 < niter) sts_tile((i + 1) & 1);
        __syncthreads();
    }

    // epilogue: C-frag (rows g,g+8; cols 2t,2t+1) -> global with bias
#pragma unroll
    for (int i = 0; i < 2; i++) {
        const int mrow = bm + wm * 32 + i * 16;
#pragma unroll
        for (int j = 0; j < 8; j++) {
            const int nb = bn + wn * 64 + j * 8 + t * 2;
            const float bx = bias[nb], by = bias[nb + 1];
#pragma unroll
            for (int h = 0; h < 2; h++) {
                const int row = mrow + g + h * 8;
                float2 v;
                v.x = acc[i][j][h * 2 + 0] + bx;
                v.y = acc[i][j][h * 2 + 1] + by;
                if (MODE == 0) {
                    const int which = nb >> 10;
                    const int c1 = nb & 1023;
                    const int hh = c1 >> 6, d = c1 & 63;
                    const int b = row >> 11, tt = row & 2047;
                    float* dst = (which == 0) ? g_q : (which == 1) ? g_k : g_v;
                    *(float2*)&dst[(((size_t)(b * HH + hh)) * TT + tt) * DD + d] = v;
                } else {
                    *(float2*)&Cout[(size_t)row * N + nb] = v;
                }
            }
        }
    }
}

// ---------------------------------------------------------------------------
// Causal flash attention, tf32 mma.sync. One block = (b,h) x 64-query tile.
// 128 threads (4 warps); warp w owns query rows [w*16, w*16+16).
// Q fragments preloaded into registers (tf32) -> no Q LDS in the loop.
// Smem (dynamic, u32): Ks[64*68], Vs[64*72], Ps[64*68] = 53248 B.
// ---------------------------------------------------------------------------
__global__ __launch_bounds__(128) void flash_mma()
{
    extern __shared__ uint32_t sm[];
    uint32_t* Ks = sm;               // [64][68]
    uint32_t* Vs = Ks + 64 * 68;     // [64][72]
    uint32_t* Ps = Vs + 64 * 72;     // [64][68]

    const int qt = blockIdx.x, bh = blockIdx.y;
    const int tid = threadIdx.x, lane = tid & 31, w = tid >> 5;
    const int g = lane >> 2, t = lane & 3;
    const int mr = w * 16;

    // Q fragments straight from gmem (one time)
    const float* qb = g_q + ((size_t)bh * TT + qt * 64) * DD;
    uint32_t qF[8][4];
#pragma unroll
    for (int ks = 0; ks < 8; ks++) {
        const int kk = ks << 3;
        qF[ks][0] = f2tf32(qb[(mr + g) * 64 + kk + t]);
        qF[ks][1] = f2tf32(qb[(mr + 8 + g) * 64 + kk + t]);
        qF[ks][2] = f2tf32(qb[(mr + g) * 64 + kk + t + 4]);
        qF[ks][3] = f2tf32(qb[(mr + 8 + g) * 64 + kk + t + 4]);
    }

    float accO[8][4];
#pragma unroll
    for (int j = 0; j < 8; j++)
#pragma unroll
        for (int c = 0; c < 4; c++) accO[j][c] = 0.f;
    float m0 = -INFINITY, m1 = -INFINITY, l0 = 0.f, l1 = 0.f;

    const float scale = 0.125f;

    for (int kt = 0; kt <= qt; kt++) {
        const float* kb = g_k + ((size_t)bh * TT + kt * 64) * DD;
        const float* vb = g_v + ((size_t)bh * TT + kt * 64) * DD;
#pragma unroll
        for (int p = 0; p < 8; p++) {
            const int idx = tid + (p << 7);
            const int row = idx >> 4, c4 = (idx & 15) << 2;
            float4 a = *(const float4*)(kb + row * 64 + c4);
            uint4 u;
            u.x = f2tf32(a.x); u.y = f2tf32(a.y);
            u.z = f2tf32(a.z); u.w = f2tf32(a.w);
            *(uint4*)&Ks[row * 68 + c4] = u;
            float4 b = *(const float4*)(vb + row * 64 + c4);
            uint4 v;
            v.x = f2tf32(b.x); v.y = f2tf32(b.y);
            v.z = f2tf32(b.z); v.w = f2tf32(b.w);
            *(uint4*)&Vs[row * 72 + c4] = v;
        }
        __syncthreads();

        // S = Q @ K^T : warp computes 16x64
        float accS[8][4];
#pragma unroll
        for (int j = 0; j < 8; j++)
#pragma unroll
            for (int c = 0; c < 4; c++) accS[j][c] = 0.f;

#pragma unroll
        for (int ks = 0; ks < 8; ks++) {
            const int kk = ks << 3;
#pragma unroll
            for (int j = 0; j < 8; j++) {
                const uint32_t b0 = Ks[(j * 8 + g) * 68 + kk + t];
                const uint32_t b1 = Ks[(j * 8 + g) * 68 + kk + t + 4];
                mma8(accS[j], qF[ks], b0, b1);
            }
        }

        // scale + causal mask (diagonal tile only)
        const int r0l = mr + g, r1l = mr + 8 + g;
        if (kt == qt) {
#pragma unroll
            for (int j = 0; j < 8; j++) {
                const int cb = j * 8 + 2 * t;
                accS[j][0] = (cb     <= r0l) ? accS[j][0] * scale : -1e30f;
                accS[j][1] = (cb + 1 <= r0l) ? accS[j][1] * scale : -1e30f;
                accS[j][2] = (cb     <= r1l) ? accS[j][2] * scale : -1e30f;
                accS[j][3] = (cb + 1 <= r1l) ? accS[j][3] * scale : -1e30f;
            }
        } else {
#pragma unroll
            for (int j = 0; j < 8; j++)
#pragma unroll
                for (int c = 0; c < 4; c++) accS[j][c] *= scale;
        }

        // online softmax (rows r0 = mr+g, r1 = mr+8+g; 4-lane t-group reduce)
        float mx0 = -1e30f, mx1 = -1e30f;
#pragma unroll
        for (int j = 0; j < 8; j++) {
            mx0 = fmaxf(mx0, fmaxf(accS[j][0], accS[j][1]));
            mx1 = fmaxf(mx1, fmaxf(accS[j][2], accS[j][3]));
        }
        mx0 = fmaxf(mx0, __shfl_xor_sync(0xffffffffu, mx0, 1));
        mx0 = fmaxf(mx0, __shfl_xor_sync(0xffffffffu, mx0, 2));
        mx1 = fmaxf(mx1, __shfl_xor_sync(0xffffffffu, mx1, 1));
        mx1 = fmaxf(mx1, __shfl_xor_sync(0xffffffffu, mx1, 2));

        const float mn0 = fmaxf(m0, mx0), mn1 = fmaxf(m1, mx1);
        const float al0 = __expf(m0 - mn0), al1 = __expf(m1 - mn1);
        float s0 = 0.f, s1 = 0.f;
#pragma unroll
        for (int j = 0; j < 8; j++) {
            accS[j][0] = __expf(accS[j][0] - mn0); s0 += accS[j][0];
            accS[j][1] = __expf(accS[j][1] - mn0); s0 += accS[j][1];
            accS[j][2] = __expf(accS[j][2] - mn1); s1 += accS[j][2];
            accS[j][3] = __expf(accS[j][3] - mn1); s1 += accS[j][3];
        }
        s0 += __shfl_xor_sync(0xffffffffu, s0, 1);
        s0 += __shfl_xor_sync(0xffffffffu, s0, 2);
        s1 += __shfl_xor_sync(0xffffffffu, s1, 1);
        s1 += __shfl_xor_sync(0xffffffffu, s1, 2);

        l0 = l0 * al0 + s0;  m0 = mn0;
        l1 = l1 * al1 + s1;  m1 = mn1;
#pragma unroll
        for (int j = 0; j < 8; j++) {
            accO[j][0] *= al0; accO[j][1] *= al0;
            accO[j][2] *= al1; accO[j][3] *= al1;
        }

        // P -> smem (tf32), per-warp private rows
        uint32_t* Pw0 = Ps + (mr + g) * 68;
        uint32_t* Pw1 = Ps + (mr + 8 + g) * 68;
#pragma unroll
        for (int j = 0; j < 8; j++) {
            const int cb = j * 8 + 2 * t;
            Pw0[cb]     = f2tf32(accS[j][0]);
            Pw0[cb + 1] = f2tf32(accS[j][1]);
            Pw1[cb]     = f2tf32(accS[j][2]);
            Pw1[cb + 1] = f2tf32(accS[j][3]);
        }
        __syncwarp();

        // O += P @ V
#pragma unroll
        for (int ks = 0; ks < 8; ks++) {
            const int kk = ks << 3;
            uint32_t aF[4];
            aF[0] = Ps[(mr + g) * 68 + kk + t];
            aF[1] = Ps[(mr + 8 + g) * 68 + kk + t];
            aF[2] = Ps[(mr + g) * 68 + kk + t + 4];
            aF[3] = Ps[(mr + 8 + g) * 68 + kk + t + 4];
#pragma unroll
            for (int j = 0; j < 8; j++) {
                const uint32_t b0 = Vs[(kk + t) * 72 + j * 8 + g];
                const uint32_t b1 = Vs[(kk + t + 4) * 72 + j * 8 + g];
                mma8(accO[j], aF, b0, b1);
            }
        }
        __syncthreads();   // protect Ks/Vs before next tile load
    }

    // normalize + write to g_ao [B,T,C]
    const float inv0 = 1.f / l0, inv1 = 1.f / l1;
    const int b = bh >> 4, h = bh & 15;
    const int r0 = qt * 64 + mr + g, r1 = r0 + 8;
#pragma unroll
    for (int j = 0; j < 8; j++) {
        const int col = h * 64 + j * 8 + 2 * t;
        float2 v0, v1;
        v0.x = accO[j][0] * inv0; v0.y = accO[j][1] * inv0;
        v1.x = accO[j][2] * inv1; v1.y = accO[j][3] * inv1;
        *(float2*)&g_ao[((size_t)(b * TT + r0)) * CC + col] = v0;
        *(float2*)&g_ao[((size_t)(b * TT + r1)) * CC + col] = v1;
    }
}

// ---------------------------------------------------------------------------
extern "C" void kernel_launch(void* const* d_in, const int* in_sizes, int n_in,
                              void* d_out, int out_size)
{
    const float* x  = (const float*)d_in[0];   // [4,2048,1024]
    const float* Wa = (const float*)d_in[1];   // [1024,3072]
    const float* ba = (const float*)d_in[2];   // [3072]
    const float* Wp = (const float*)d_in[3];   // [1024,1024]
    const float* bp = (const float*)d_in[4];   // [1024]
    float* out = (float*)d_out;                // [4,2048,1024]

    void* p_ao = nullptr;
    cudaGetSymbolAddress(&p_ao, g_ao);

    const int GEMM_SMEM = (2 * (128 * 36) + 2 * (32 * 136)) * (int)sizeof(uint32_t); // 71680
    cudaFuncSetAttribute(gemm_mma<0>, cudaFuncAttributeMaxDynamicSharedMemorySize,
                         GEMM_SMEM);
    cudaFuncSetAttribute(gemm_mma<1>, cudaFuncAttributeMaxDynamicSharedMemorySize,
                         GEMM_SMEM);

    // 1) QKV GEMM + bias, scatter to [B,H,T,D]  (tf32 mma.sync, pipelined)
    gemm_mma<0><<<dim3(3072 / 128, 8192 / 128), 256, GEMM_SMEM>>>(
        x, Wa, ba, nullptr, 8192, 3072, 1024);

    // 2) causal flash attention (tf32 mma.sync, Q in registers)
    const int FLASH_SMEM = (64 * 68 + 64 * 72 + 64 * 68) * (int)sizeof(uint32_t); // 53248
    cudaFuncSetAttribute(flash_mma, cudaFuncAttributeMaxDynamicSharedMemorySize,
                         FLASH_SMEM);
    flash_mma<<<dim3(TT / 64, BB * HH), 128, FLASH_SMEM>>>();

    // 3) output projection + bias  (tf32 mma.sync, pipelined)
    gemm_mma<1><<<dim3(1024 / 128, 8192 / 128), 256, GEMM_SMEM>>>(
        (const float*)p_ao, Wp, bp, out, 8192, 1024, 1024);
}

// round 5
// speedup vs baseline: 4.9894x; 1.2138x over previous
#include <cuda_runtime.h>
#include <math.h>
#include <cstdint>

#define BB 4
#define TT 2048
#define CC 1024
#define HH 16
#define DD 64

// Scratch (static device globals — allocation-guard safe)
__device__ float g_q[BB * HH * TT * DD];   // [B,H,T,D] (tf32-rounded bits)
__device__ float g_k[BB * HH * TT * DD];
__device__ float g_v[BB * HH * TT * DD];
__device__ float g_ao[BB * TT * CC];       // attention out, [B,T,C] (tf32 bits)
__device__ float g_xc[BB * TT * CC];       // x  pre-rounded to tf32 bits
__device__ float g_wac[CC * 3 * CC];       // W_attn pre-rounded
__device__ float g_wpc[CC * CC];           // W_proj pre-rounded

// ---------------------------------------------------------------------------
__device__ __forceinline__ uint32_t f2tf32(float x) {
    uint32_t u;
    asm("cvt.rna.tf32.f32 %0, %1;" : "=r"(u) : "f"(x));
    return u;
}
__device__ __forceinline__ uint32_t smem_u32(const void* p) {
    uint32_t a;
    asm("{ .reg .u64 t; cvta.to.shared.u64 t, %1; cvt.u32.u64 %0, t; }"
        : "=r"(a) : "l"(p));
    return a;
}
__device__ __forceinline__ void cp16(uint32_t dst, const void* src) {
    asm volatile("cp.async.cg.shared.global [%0], [%1], 16;"
                 :: "r"(dst), "l"(src));
}
#define CP_COMMIT() asm volatile("cp.async.commit_group;" ::: "memory")
#define CP_WAIT(n)  asm volatile("cp.async.wait_group %0;" :: "n"(n) : "memory")

// m16n8k8 tf32 MMA, D += A*B (fp32 accumulate, in-place)
__device__ __forceinline__ void mma8(float* d, const uint32_t* a,
                                     uint32_t b0, uint32_t b1) {
    asm volatile(
        "mma.sync.aligned.m16n8k8.row.col.f32.tf32.tf32.f32 "
        "{%0,%1,%2,%3}, {%4,%5,%6,%7}, {%8,%9}, {%0,%1,%2,%3};"
        : "+f"(d[0]), "+f"(d[1]), "+f"(d[2]), "+f"(d[3])
        : "r"(a[0]), "r"(a[1]), "r"(a[2]), "r"(a[3]), "r"(b0), "r"(b1));
}

// ---------------------------------------------------------------------------
// tf32 pre-round pass: dst[i] = round_tf32(src[i])
// ---------------------------------------------------------------------------
__global__ __launch_bounds__(256) void cvt_k(const float* __restrict__ src,
                                             float* __restrict__ dst, int n4)
{
    const int i = blockIdx.x * 256 + threadIdx.x;
    if (i < n4) {
        float4 a = *(const float4*)(src + (size_t)i * 4);
        uint4 u;
        u.x = f2tf32(a.x); u.y = f2tf32(a.y);
        u.z = f2tf32(a.z); u.w = f2tf32(a.w);
        *(uint4*)(dst + (size_t)i * 4) = u;
    }
}

// ---------------------------------------------------------------------------
// tf32 mma.sync GEMM, 3-stage cp.async pipeline. Inputs pre-rounded to tf32.
// C[M,N] = A[M,K] @ B[K,N] + bias. 128x128 tile, BK=32, 256 thr (8 warps 4x2).
// Smem (u32): As[3][128*36] + Bs[3][32*136] = 107520 B. 2 CTAs/SM.
// MODE 0: scatter tf32-rounded into g_q/g_k/g_v.  MODE 1: Cout fp32 row-major.
// ---------------------------------------------------------------------------
template <int MODE>
__global__ __launch_bounds__(256, 2) void gemm_mma(
    const float* __restrict__ A, const float* __restrict__ Bw,
    const float* __restrict__ bias, float* __restrict__ Cout,
    int M, int N, int K)
{
    extern __shared__ uint32_t sm[];
    const uint32_t smb = smem_u32(sm);
    const int tid  = threadIdx.x;
    const int lane = tid & 31, warp = tid >> 5;
    const int wm = warp >> 1, wn = warp & 1;
    const int g = lane >> 2, t = lane & 3;
    const int bm = blockIdx.y * 128, bn = blockIdx.x * 128;

    const int arow = tid >> 3, acq = (tid & 7) << 2;   // A: rows arow+32p
    const int bkr  = tid >> 5, bnq = (tid & 31) << 2;  // B: rows bkr+8p

    float acc[2][8][4];
#pragma unroll
    for (int i = 0; i < 2; i++)
#pragma unroll
        for (int j = 0; j < 8; j++)
#pragma unroll
            for (int c = 0; c < 4; c++) acc[i][j][c] = 0.f;

    auto issue = [&](int it) {
        const int s = it % 3;
        const int k0 = it << 5;
        const uint32_t as = smb + (uint32_t)(s * 4608) * 4;
        const uint32_t bs = smb + (uint32_t)(13824 + s * 4352) * 4;
#pragma unroll
        for (int p = 0; p < 4; p++) {
            cp16(as + (uint32_t)((arow + 32 * p) * 36 + acq) * 4,
                 A + (size_t)(bm + arow + 32 * p) * K + k0 + acq);
            cp16(bs + (uint32_t)((bkr + 8 * p) * 136 + bnq) * 4,
                 Bw + (size_t)(k0 + bkr + 8 * p) * N + bn + bnq);
        }
    };
    auto compute = [&](int s) {
        const uint32_t* As = sm + s * 4608;
        const uint32_t* Bs = sm + 13824 + s * 4352;
#pragma unroll
        for (int ks = 0; ks < 4; ks++) {
            const int kk = ks << 3;
            uint32_t aF[2][4];
#pragma unroll
            for (int i = 0; i < 2; i++) {
                const int mr = wm * 32 + i * 16;
                aF[i][0] = As[(mr + g) * 36 + kk + t];
                aF[i][1] = As[(mr + 8 + g) * 36 + kk + t];
                aF[i][2] = As[(mr + g) * 36 + kk + t + 4];
                aF[i][3] = As[(mr + 8 + g) * 36 + kk + t + 4];
            }
#pragma unroll
            for (int j = 0; j < 8; j++) {
                const int nb = wn * 64 + j * 8;
                const uint32_t b0 = Bs[(kk + t) * 136 + nb + g];
                const uint32_t b1 = Bs[(kk + t + 4) * 136 + nb + g];
                mma8(acc[0][j], aF[0], b0, b1);
                mma8(acc[1][j], aF[1], b0, b1);
            }
        }
    };

    const int niter = K >> 5;         // 32
    issue(0); CP_COMMIT();
    issue(1); CP_COMMIT();
    for (int i = 0; i < niter; i++) {
        CP_WAIT(1);
        __syncthreads();
        if (i + 2 < niter) issue(i + 2);
        CP_COMMIT();
        compute(i % 3);
    }

    // epilogue
#pragma unroll
    for (int i = 0; i < 2; i++) {
        const int mrow = bm + wm * 32 + i * 16;
#pragma unroll
        for (int j = 0; j < 8; j++) {
            const int nb = bn + wn * 64 + j * 8 + t * 2;
            const float bx = bias[nb], by = bias[nb + 1];
#pragma unroll
            for (int h = 0; h < 2; h++) {
                const int row = mrow + g + h * 8;
                float2 v;
                v.x = acc[i][j][h * 2 + 0] + bx;
                v.y = acc[i][j][h * 2 + 1] + by;
                if (MODE == 0) {
                    // round to tf32 bits so flash can consume without cvt
                    v.x = __uint_as_float(f2tf32(v.x));
                    v.y = __uint_as_float(f2tf32(v.y));
                    const int which = nb >> 10;
                    const int c1 = nb & 1023;
                    const int hh = c1 >> 6, d = c1 & 63;
                    const int b = row >> 11, tt = row & 2047;
                    float* dst = (which == 0) ? g_q : (which == 1) ? g_k : g_v;
                    *(float2*)&dst[(((size_t)(b * HH + hh)) * TT + tt) * DD + d] = v;
                } else {
                    *(float2*)&Cout[(size_t)row * N + nb] = v;
                }
            }
        }
    }
}

// ---------------------------------------------------------------------------
// Causal flash attention, tf32 mma.sync. One block = (b,h) x 64-query tile.
// 128 threads (4 warps); warp w owns query rows [w*16, w*16+16).
// Q fragments in registers; K/V tiles cp.async'd (inputs pre-tf32-rounded).
// Smem (u32): Ks[64*68], Vs[64*72], Ps[64*68] = 53248 B.
// ---------------------------------------------------------------------------
__global__ __launch_bounds__(128) void flash_mma()
{
    extern __shared__ uint32_t sm[];
    uint32_t* Ks = sm;               // [64][68]
    uint32_t* Vs = Ks + 64 * 68;     // [64][72]
    uint32_t* Ps = Vs + 64 * 72;     // [64][68]
    const uint32_t ks_b = smem_u32(Ks);
    const uint32_t vs_b = smem_u32(Vs);

    const int qt = blockIdx.x, bh = blockIdx.y;
    const int tid = threadIdx.x, lane = tid & 31, w = tid >> 5;
    const int g = lane >> 2, t = lane & 3;
    const int mr = w * 16;

    // Q fragments straight from gmem (pre-rounded tf32 bits)
    const float* qb = g_q + ((size_t)bh * TT + qt * 64) * DD;
    uint32_t qF[8][4];
#pragma unroll
    for (int ks = 0; ks < 8; ks++) {
        const int kk = ks << 3;
        qF[ks][0] = __float_as_uint(qb[(mr + g) * 64 + kk + t]);
        qF[ks][1] = __float_as_uint(qb[(mr + 8 + g) * 64 + kk + t]);
        qF[ks][2] = __float_as_uint(qb[(mr + g) * 64 + kk + t + 4]);
        qF[ks][3] = __float_as_uint(qb[(mr + 8 + g) * 64 + kk + t + 4]);
    }

    float accO[8][4];
#pragma unroll
    for (int j = 0; j < 8; j++)
#pragma unroll
        for (int c = 0; c < 4; c++) accO[j][c] = 0.f;
    float m0 = -INFINITY, m1 = -INFINITY, l0 = 0.f, l1 = 0.f;

    const float scale = 0.125f;

    for (int kt = 0; kt <= qt; kt++) {
        const float* kb = g_k + ((size_t)bh * TT + kt * 64) * DD;
        const float* vb = g_v + ((size_t)bh * TT + kt * 64) * DD;
#pragma unroll
        for (int p = 0; p < 8; p++) {
            const int idx = tid + (p << 7);
            const int row = idx >> 4, c4 = (idx & 15) << 2;
            cp16(ks_b + (uint32_t)(row * 68 + c4) * 4, kb + row * 64 + c4);
            cp16(vs_b + (uint32_t)(row * 72 + c4) * 4, vb + row * 64 + c4);
        }
        CP_COMMIT();
        CP_WAIT(0);
        __syncthreads();

        // S = Q @ K^T : warp computes 16x64
        float accS[8][4];
#pragma unroll
        for (int j = 0; j < 8; j++)
#pragma unroll
            for (int c = 0; c < 4; c++) accS[j][c] = 0.f;

#pragma unroll
        for (int ks = 0; ks < 8; ks++) {
            const int kk = ks << 3;
#pragma unroll
            for (int j = 0; j < 8; j++) {
                const uint32_t b0 = Ks[(j * 8 + g) * 68 + kk + t];
                const uint32_t b1 = Ks[(j * 8 + g) * 68 + kk + t + 4];
                mma8(accS[j], qF[ks], b0, b1);
            }
        }

        // scale + causal mask (diagonal tile only)
        const int r0l = mr + g, r1l = mr + 8 + g;
        if (kt == qt) {
#pragma unroll
            for (int j = 0; j < 8; j++) {
                const int cb = j * 8 + 2 * t;
                accS[j][0] = (cb     <= r0l) ? accS[j][0] * scale : -1e30f;
                accS[j][1] = (cb + 1 <= r0l) ? accS[j][1] * scale : -1e30f;
                accS[j][2] = (cb     <= r1l) ? accS[j][2] * scale : -1e30f;
                accS[j][3] = (cb + 1 <= r1l) ? accS[j][3] * scale : -1e30f;
            }
        } else {
#pragma unroll
            for (int j = 0; j < 8; j++)
#pragma unroll
                for (int c = 0; c < 4; c++) accS[j][c] *= scale;
        }

        // online softmax (rows r0 = mr+g, r1 = mr+8+g; 4-lane t-group reduce)
        float mx0 = -1e30f, mx1 = -1e30f;
#pragma unroll
        for (int j = 0; j < 8; j++) {
            mx0 = fmaxf(mx0, fmaxf(accS[j][0], accS[j][1]));
            mx1 = fmaxf(mx1, fmaxf(accS[j][2], accS[j][3]));
        }
        mx0 = fmaxf(mx0, __shfl_xor_sync(0xffffffffu, mx0, 1));
        mx0 = fmaxf(mx0, __shfl_xor_sync(0xffffffffu, mx0, 2));
        mx1 = fmaxf(mx1, __shfl_xor_sync(0xffffffffu, mx1, 1));
        mx1 = fmaxf(mx1, __shfl_xor_sync(0xffffffffu, mx1, 2));

        const float mn0 = fmaxf(m0, mx0), mn1 = fmaxf(m1, mx1);
        const float al0 = __expf(m0 - mn0), al1 = __expf(m1 - mn1);
        float s0 = 0.f, s1 = 0.f;
#pragma unroll
        for (int j = 0; j < 8; j++) {
            accS[j][0] = __expf(accS[j][0] - mn0); s0 += accS[j][0];
            accS[j][1] = __expf(accS[j][1] - mn0); s0 += accS[j][1];
            accS[j][2] = __expf(accS[j][2] - mn1); s1 += accS[j][2];
            accS[j][3] = __expf(accS[j][3] - mn1); s1 += accS[j][3];
        }
        s0 += __shfl_xor_sync(0xffffffffu, s0, 1);
        s0 += __shfl_xor_sync(0xffffffffu, s0, 2);
        s1 += __shfl_xor_sync(0xffffffffu, s1, 1);
        s1 += __shfl_xor_sync(0xffffffffu, s1, 2);

        l0 = l0 * al0 + s0;  m0 = mn0;
        l1 = l1 * al1 + s1;  m1 = mn1;
#pragma unroll
        for (int j = 0; j < 8; j++) {
            accO[j][0] *= al0; accO[j][1] *= al0;
            accO[j][2] *= al1; accO[j][3] *= al1;
        }

        // P -> smem (tf32), per-warp private rows
        uint32_t* Pw0 = Ps + (mr + g) * 68;
        uint32_t* Pw1 = Ps + (mr + 8 + g) * 68;
#pragma unroll
        for (int j = 0; j < 8; j++) {
            const int cb = j * 8 + 2 * t;
            Pw0[cb]     = f2tf32(accS[j][0]);
            Pw0[cb + 1] = f2tf32(accS[j][1]);
            Pw1[cb]     = f2tf32(accS[j][2]);
            Pw1[cb + 1] = f2tf32(accS[j][3]);
        }
        __syncwarp();

        // O += P @ V
#pragma unroll
        for (int ks = 0; ks < 8; ks++) {
            const int kk = ks << 3;
            uint32_t aF[4];
            aF[0] = Ps[(mr + g) * 68 + kk + t];
            aF[1] = Ps[(mr + 8 + g) * 68 + kk + t];
            aF[2] = Ps[(mr + g) * 68 + kk + t + 4];
            aF[3] = Ps[(mr + 8 + g) * 68 + kk + t + 4];
#pragma unroll
            for (int j = 0; j < 8; j++) {
                const uint32_t b0 = Vs[(kk + t) * 72 + j * 8 + g];
                const uint32_t b1 = Vs[(kk + t + 4) * 72 + j * 8 + g];
                mma8(accO[j], aF, b0, b1);
            }
        }
        __syncthreads();   // protect Ks/Vs before next tile load
    }

    // normalize + write to g_ao [B,T,C], tf32-rounded for the proj GEMM
    const float inv0 = 1.f / l0, inv1 = 1.f / l1;
    const int b = bh >> 4, h = bh & 15;
    const int r0 = qt * 64 + mr + g, r1 = r0 + 8;
#pragma unroll
    for (int j = 0; j < 8; j++) {
        const int col = h * 64 + j * 8 + 2 * t;
        float2 v0, v1;
        v0.x = __uint_as_float(f2tf32(accO[j][0] * inv0));
        v0.y = __uint_as_float(f2tf32(accO[j][1] * inv0));
        v1.x = __uint_as_float(f2tf32(accO[j][2] * inv1));
        v1.y = __uint_as_float(f2tf32(accO[j][3] * inv1));
        *(float2*)&g_ao[((size_t)(b * TT + r0)) * CC + col] = v0;
        *(float2*)&g_ao[((size_t)(b * TT + r1)) * CC + col] = v1;
    }
}

// ---------------------------------------------------------------------------
extern "C" void kernel_launch(void* const* d_in, const int* in_sizes, int n_in,
                              void* d_out, int out_size)
{
    const float* x  = (const float*)d_in[0];   // [4,2048,1024]
    const float* Wa = (const float*)d_in[1];   // [1024,3072]
    const float* ba = (const float*)d_in[2];   // [3072]
    const float* Wp = (const float*)d_in[3];   // [1024,1024]
    const float* bp = (const float*)d_in[4];   // [1024]
    float* out = (float*)d_out;                // [4,2048,1024]

    void *p_ao, *p_xc, *p_wac, *p_wpc;
    cudaGetSymbolAddress(&p_ao, g_ao);
    cudaGetSymbolAddress(&p_xc, g_xc);
    cudaGetSymbolAddress(&p_wac, g_wac);
    cudaGetSymbolAddress(&p_wpc, g_wpc);

    // 0) pre-round inputs to tf32 bits
    const int nx = BB * TT * CC / 4, nwa = CC * 3 * CC / 4, nwp = CC * CC / 4;
    cvt_k<<<(nx + 255) / 256, 256>>>(x, (float*)p_xc, nx);
    cvt_k<<<(nwa + 255) / 256, 256>>>(Wa, (float*)p_wac, nwa);
    cvt_k<<<(nwp + 255) / 256, 256>>>(Wp, (float*)p_wpc, nwp);

    const int GEMM_SMEM = (3 * 4608 + 3 * 4352) * (int)sizeof(uint32_t); // 107520
    cudaFuncSetAttribute(gemm_mma<0>, cudaFuncAttributeMaxDynamicSharedMemorySize,
                         GEMM_SMEM);
    cudaFuncSetAttribute(gemm_mma<1>, cudaFuncAttributeMaxDynamicSharedMemorySize,
                         GEMM_SMEM);

    // 1) QKV GEMM + bias, scatter tf32-rounded to [B,H,T,D]
    gemm_mma<0><<<dim3(3072 / 128, 8192 / 128), 256, GEMM_SMEM>>>(
        (const float*)p_xc, (const float*)p_wac, ba, nullptr, 8192, 3072, 1024);

    // 2) causal flash attention
    const int FLASH_SMEM = (64 * 68 + 64 * 72 + 64 * 68) * (int)sizeof(uint32_t);
    cudaFuncSetAttribute(flash_mma, cudaFuncAttributeMaxDynamicSharedMemorySize,
                         FLASH_SMEM);
    flash_mma<<<dim3(TT / 64, BB * HH), 128, FLASH_SMEM>>>();

    // 3) output projection + bias (fp32 out)
    gemm_mma<1><<<dim3(1024 / 128, 8192 / 128), 256, GEMM_SMEM>>>(
        (const float*)p_ao, (const float*)p_wpc, bp, out, 8192, 1024, 1024);
}